// round 5
// baseline (speedup 1.0000x reference)
#include <cuda_runtime.h>
#include <cstddef>

#define FULLMASK 0xffffffffu
typedef unsigned long long u64;

// T=128, D=768, HID=768, L=3, OUT=768, LH=2304
__device__ float g_H[128 * 2304];        // h_cat per step
__device__ float g_wfT[2304 * 768];      // transposed w_final
__device__ float g_part[12 * 128 * 768]; // split-K partials

// ---------------------------------------------------------------- helpers
__device__ __forceinline__ unsigned smem_u32(const void* p) {
    unsigned a;
    asm("{ .reg .u64 t; cvta.to.shared.u64 t, %1; cvt.u32.u64 %0, t; }"
        : "=r"(a) : "l"(p));
    return a;
}
__device__ __forceinline__ void cp_async16(unsigned d, const void* src) {
    asm volatile("cp.async.ca.shared.global [%0], [%1], 16;\n" :: "r"(d), "l"(src));
}
__device__ __forceinline__ void cp_commit() { asm volatile("cp.async.commit_group;\n" ::); }
__device__ __forceinline__ void cp_wait0()  { asm volatile("cp.async.wait_group 0;\n" ::); }

__device__ __forceinline__ u64 fma2(u64 a, u64 b, u64 c) {
    u64 d; asm("fma.rn.f32x2 %0, %1, %2, %3;" : "=l"(d) : "l"(a), "l"(b), "l"(c)); return d;
}
__device__ __forceinline__ u64 mul2(u64 a, u64 b) {
    u64 d; asm("mul.rn.f32x2 %0, %1, %2;" : "=l"(d) : "l"(a), "l"(b)); return d;
}
__device__ __forceinline__ u64 pk2(float x, float y) {
    u64 d; asm("mov.b64 %0, {%1, %2};" : "=l"(d) : "f"(x), "f"(y)); return d;
}
__device__ __forceinline__ float2 up2(u64 v) {
    float2 r; asm("mov.b64 {%0, %1}, %2;" : "=f"(r.x), "=f"(r.y) : "l"(v)); return r;
}
__device__ __forceinline__ void lds2(u64& a, u64& b, unsigned addr) {
    asm volatile("ld.shared.v2.b64 {%0, %1}, [%2];" : "=l"(a), "=l"(b) : "r"(addr));
}
__device__ __forceinline__ void ldg2(u64& a, u64& b, const float* p) {
    asm volatile("ld.global.nc.v2.b64 {%0, %1}, [%2];" : "=l"(a), "=l"(b) : "l"(p));
}
__device__ __forceinline__ float sig_fast(float z) {
    float e = __expf(-z);
    return __fdividef(1.0f, 1.0f + e);
}
__device__ __forceinline__ float wredsum(float a) {
#pragma unroll
    for (int m = 16; m >= 1; m >>= 1) a += __shfl_xor_sync(FULLMASK, a, m);
    return a;
}

// ---------------------------------------------------------------- shared memory
struct ScanSmem { float wxb[2048]; __align__(16) float xb[2 * 4 * 768]; };  // 32.7KB
union Smem {
    ScanSmem s;
    float tile[64 * 65];          // transpose prologue
};

// ---------------------------------------------------------------- pipelined scan step
// u = q_stale . x_t (h-independent); v = e . (x_{t-1} o x_t) (h-independent);
// pre = dsc[J]*(u + sp*v) + wxb ; pending update q += sp*(e o x_{t-1}) off-chain.
template <int J>
__device__ __forceinline__ void scan_step(
    int c, unsigned xcs, const float* __restrict__ wxb,
    u64 (&cur)[12], u64 (&prv)[12],
    u64 (&q0)[12], u64 (&q1)[12], const u64 (&e0)[12], const u64 (&e1)[12],
    const float (&dsc)[4], const float (&us)[4],
    float& sp0, float& sp1, u64& sp02, u64& sp12,
    int lane, int r0, int gc0)
{
    const int t = c * 4 + J;
    const unsigned xa = xcs + J * 3072 + 16 * lane;
#pragma unroll
    for (int kk = 0; kk < 6; kk++) lds2(cur[2 * kk], cur[2 * kk + 1], xa + 512 * kk);

    // u dots (stale state, h-independent)
    u64 ua = 0, ub = 0, uc = 0, ud = 0;
#pragma unroll
    for (int k = 0; k < 6; k++) {
        ua = fma2(q0[2 * k], cur[2 * k], ua);
        uc = fma2(q0[2 * k + 1], cur[2 * k + 1], uc);
        ub = fma2(q1[2 * k], cur[2 * k], ub);
        ud = fma2(q1[2 * k + 1], cur[2 * k + 1], ud);
    }
    // v dots (correction; z shared across both rows)
    u64 va = 0, vb = 0, vc = 0, vd = 0;
#pragma unroll
    for (int k = 0; k < 6; k++) {
        u64 z0 = mul2(prv[2 * k], cur[2 * k]);
        u64 z1 = mul2(prv[2 * k + 1], cur[2 * k + 1]);
        va = fma2(e0[2 * k], z0, va); vc = fma2(e0[2 * k + 1], z1, vc);
        vb = fma2(e1[2 * k], z0, vb); vd = fma2(e1[2 * k + 1], z1, vd);
    }
    // apply pending update (h_{t-1} known since last step; off the critical chain)
#pragma unroll
    for (int k = 0; k < 12; k++) {
        q0[k] = fma2(sp02, mul2(e0[k], prv[k]), q0[k]);
        q1[k] = fma2(sp12, mul2(e1[k], prv[k]), q1[k]);
    }
    // per-lane combine, then reduce
    float2 fua = up2(ua), fuc = up2(uc), fub = up2(ub), fud = up2(ud);
    float2 fva = up2(va), fvc = up2(vc), fvb = up2(vb), fvd = up2(vd);
    float r0v = ((fua.x + fua.y) + (fuc.x + fuc.y))
              + sp0 * ((fva.x + fva.y) + (fvc.x + fvc.y));
    float r1v = ((fub.x + fub.y) + (fud.x + fud.y))
              + sp1 * ((fvb.x + fvb.y) + (fvd.x + fvd.y));
    r0v = wredsum(r0v);
    r1v = wredsum(r1v);
    const float2 wx = *(const float2*)(wxb + t * 16 + r0);
    float h0 = sig_fast(fmaf(dsc[J], r0v, wx.x));
    float h1 = sig_fast(fmaf(dsc[J], r1v, wx.y));
    if (lane == 0) {
        float2 hv; hv.x = h0; hv.y = h1;
        *(float2*)(g_H + (size_t)t * 2304 + gc0) = hv;
    }
    sp0 = h0 * us[(J + 1) & 3];
    sp1 = h1 * us[(J + 1) & 3];
    sp02 = pk2(sp0, sp0);
    sp12 = pk2(sp1, sp1);
}

// ---------------------------------------------------------------- kernel 1: transpose prologue + scan
// 144 CTAs; CTA j: layer l=j/48, rows [(j%48)*16,+16). Warp w owns rows 2w,2w+1.
__global__ void __launch_bounds__(256, 1) k_scan(
    const float* __restrict__ x_seq, const float* __restrict__ W,
    const float* __restrict__ b, const float* __restrict__ lam,
    const float* __restrict__ eta0, const float* __restrict__ eta1p,
    const float* __restrict__ eta2, const float* __restrict__ P_init,
    const float* __restrict__ wf)
{
    __shared__ Smem sm;
    const int tid = threadIdx.x;
    const int bid = blockIdx.x;

    // ---- prologue: wf transpose, 3 tiles of 64x64 per CTA (432 total)
    {
        const int rr = tid >> 4, cc = (tid & 15) * 4;
#pragma unroll 1
        for (int it = 0; it < 3; it++) {
            const int tt = bid * 3 + it;
            const int o0 = (tt % 12) * 64;
            const int j0 = (tt / 12) * 64;
#pragma unroll
            for (int i = 0; i < 4; i++) {
                int r = rr + 16 * i;
                float4 v = *(const float4*)(wf + (size_t)(o0 + r) * 2304 + j0 + cc);
                sm.tile[r * 65 + cc + 0] = v.x; sm.tile[r * 65 + cc + 1] = v.y;
                sm.tile[r * 65 + cc + 2] = v.z; sm.tile[r * 65 + cc + 3] = v.w;
            }
            __syncthreads();
#pragma unroll
            for (int i = 0; i < 4; i++) {
                int jj = rr + 16 * i;
                float4 v;
                v.x = sm.tile[(cc + 0) * 65 + jj];
                v.y = sm.tile[(cc + 1) * 65 + jj];
                v.z = sm.tile[(cc + 2) * 65 + jj];
                v.w = sm.tile[(cc + 3) * 65 + jj];
                *(float4*)(g_wfT + (size_t)(j0 + jj) * 768 + o0 + cc) = v;
            }
            __syncthreads();
        }
    }

    // ---- scan
    const int l  = bid / 48;
    const int rb = (bid % 48) * 16;
    const int w = tid >> 5, lane = tid & 31;
    const int r0 = 2 * w;
    const int gr0 = rb + r0, gr1 = gr0 + 1;
    const float* Wl = W + (size_t)l * 589824;
    const int cb = 4 * lane;
    float* wxb = sm.s.wxb;

    // WXB precompute: wxb[t][r] = W[r,:]@x_t + b[r]
    {
        u64 wv0[12], wv1[12];
#pragma unroll
        for (int kk = 0; kk < 6; kk++) {
            ldg2(wv0[2 * kk], wv0[2 * kk + 1], Wl + (size_t)gr0 * 768 + cb + 128 * kk);
            ldg2(wv1[2 * kk], wv1[2 * kk + 1], Wl + (size_t)gr1 * 768 + cb + 128 * kk);
        }
        const float bb0 = b[l * 768 + gr0], bb1 = b[l * 768 + gr1];

        float4* xf4 = (float4*)sm.s.xb;
        const float4* xs4 = (const float4*)x_seq;
        const unsigned xfs = smem_u32(sm.s.xb);
        for (int c0 = 0; c0 < 128; c0 += 8) {
#pragma unroll
            for (int i = 0; i < 6; i++)
                xf4[tid + 256 * i] = xs4[(size_t)c0 * 192 + tid + 256 * i];
            __syncthreads();
#pragma unroll
            for (int tt = 0; tt < 8; tt++) {
                const unsigned xa = xfs + tt * 3072 + 16 * lane;
                u64 a0 = 0, a1 = 0, a2 = 0, a3 = 0;
#pragma unroll
                for (int kk = 0; kk < 6; kk++) {
                    u64 x0, x1; lds2(x0, x1, xa + 512 * kk);
                    a0 = fma2(wv0[2 * kk], x0, a0); a2 = fma2(wv0[2 * kk + 1], x1, a2);
                    a1 = fma2(wv1[2 * kk], x0, a1); a3 = fma2(wv1[2 * kk + 1], x1, a3);
                }
                float2 f0 = up2(a0), f1 = up2(a1), f2 = up2(a2), f3 = up2(a3);
                float s0 = wredsum((f0.x + f0.y) + (f2.x + f2.y));
                float s1 = wredsum((f1.x + f1.y) + (f3.x + f3.y));
                if (lane == 0) {
                    wxb[(c0 + tt) * 16 + r0]     = s0 + bb0;
                    wxb[(c0 + tt) * 16 + r0 + 1] = s1 + bb1;
                }
            }
            __syncthreads();
        }
    }

    // persistent state (unified A/M): A: q=P, e=eta, escal=1 | M: q=W.P, e=W, escal=eta1
    u64 q0[12], q1[12], e0[12], e1[12];
    const float* Pl = P_init + (size_t)l * 589824;
#pragma unroll
    for (int kk = 0; kk < 6; kk++) {
        ldg2(q0[2 * kk], q0[2 * kk + 1], Pl + (size_t)gr0 * 768 + cb + 128 * kk);
        ldg2(q1[2 * kk], q1[2 * kk + 1], Pl + (size_t)gr1 * 768 + cb + 128 * kk);
    }
    const float* ep = (l == 0) ? eta0 : ((l == 2) ? eta2 : Wl);
#pragma unroll
    for (int kk = 0; kk < 6; kk++) {
        ldg2(e0[2 * kk], e0[2 * kk + 1], ep + (size_t)gr0 * 768 + cb + 128 * kk);
        ldg2(e1[2 * kk], e1[2 * kk + 1], ep + (size_t)gr1 * 768 + cb + 128 * kk);
    }
    if (l == 1) {
#pragma unroll
        for (int k = 0; k < 12; k++) { q0[k] = mul2(q0[k], e0[k]); q1[k] = mul2(q1[k], e1[k]); }
    }
    const float decay = 1.0f / (1.0f + __expf(-lam[l]));
    const float escal = (l == 1) ? eta1p[0] : 1.0f;
    const float d2v = decay * decay, d3v = d2v * decay, d4v = d2v * d2v;
    float dsc[4], us[4];
    dsc[0] = 1.f; dsc[1] = decay; dsc[2] = d2v; dsc[3] = d3v;
    // us[j]: scale applied at step j for the pending update from step j-1's h
    us[0] = escal; us[1] = escal / decay; us[2] = escal / d2v; us[3] = escal / d3v;
    const u64 d42 = pk2(d4v, d4v);
    const int gc0 = l * 768 + rb + r0;
    const unsigned xbs = smem_u32(sm.s.xb);

    u64 xA[12], xB[12];
#pragma unroll
    for (int k = 0; k < 12; k++) xB[k] = 0;   // prv for t=0 (sp=0; zeros avoid NaN)
    float sp0 = 0.f, sp1 = 0.f;
    u64 sp02 = 0, sp12 = 0;

    // preload chunk 0 (4 steps = 3072 floats)
#pragma unroll
    for (int i = 0; i < 3; i++)
        cp_async16(xbs + 16 * (tid + 256 * i), x_seq + 4 * (tid + 256 * i));
    cp_commit(); cp_wait0();
    __syncthreads();

    for (int c = 0; c < 32; c++) {
        if (c < 31) {
            const float* src = x_seq + (size_t)(c + 1) * 3072;
            unsigned dst = xbs + ((c + 1) & 1) * 12288;
#pragma unroll
            for (int i = 0; i < 3; i++)
                cp_async16(dst + 16 * (tid + 256 * i), src + 4 * (tid + 256 * i));
            cp_commit();
        }
        const unsigned xcs = xbs + (c & 1) * 12288;
        scan_step<0>(c, xcs, wxb, xA, xB, q0, q1, e0, e1, dsc, us, sp0, sp1, sp02, sp12, lane, r0, gc0);
        scan_step<1>(c, xcs, wxb, xB, xA, q0, q1, e0, e1, dsc, us, sp0, sp1, sp02, sp12, lane, r0, gc0);
        scan_step<2>(c, xcs, wxb, xA, xB, q0, q1, e0, e1, dsc, us, sp0, sp1, sp02, sp12, lane, r0, gc0);
        scan_step<3>(c, xcs, wxb, xB, xA, q0, q1, e0, e1, dsc, us, sp0, sp1, sp02, sp12, lane, r0, gc0);
        // chunk-end rescale; pending h3 update (us[0]=escal) lands post-rescale next chunk
#pragma unroll
        for (int k = 0; k < 12; k++) { q0[k] = mul2(q0[k], d42); q1[k] = mul2(q1[k], d42); }
        if (c < 31) cp_wait0();
        __syncthreads();
    }
}

// ---------------------------------------------------------------- kernel 2: readout GEMM (split-K 12)
__global__ void __launch_bounds__(256) k_gemm() {
    __shared__ __align__(16) float Hs[192 * 36];  // [192 j][32 t + pad 4]
    const int ob = blockIdx.x, tb = blockIdx.y, kb = blockIdx.z;
    const int tid = threadIdx.x;
    const int t0 = tb * 32;
#pragma unroll
    for (int i = 0; i < 24; i++) {
        int idx = tid + 256 * i;
        int tl = idx / 192, jl = idx - tl * 192;
        Hs[jl * 36 + tl] = g_H[(size_t)(t0 + tl) * 2304 + kb * 192 + jl];
    }
    __syncthreads();

    u64 acc[16];
#pragma unroll
    for (int i = 0; i < 16; i++) acc[i] = 0;

    const int o = ob * 256 + tid;
    const float* wp = g_wfT + (size_t)(kb * 192) * 768 + o;
    const unsigned hs = smem_u32(Hs);
#pragma unroll 8
    for (int j = 0; j < 192; j++) {
        float wv = __ldg(wp + (size_t)j * 768);
        u64 w2 = pk2(wv, wv);
        const unsigned ha = hs + j * 144;
#pragma unroll
        for (int u = 0; u < 8; u++) {
            u64 h0, h1; lds2(h0, h1, ha + 16 * u);
            acc[2 * u]     = fma2(w2, h0, acc[2 * u]);
            acc[2 * u + 1] = fma2(w2, h1, acc[2 * u + 1]);
        }
    }
    float* pp = g_part + (size_t)kb * 98304 + (size_t)t0 * 768 + o;
#pragma unroll
    for (int u = 0; u < 8; u++) {
        float2 v0 = up2(acc[2 * u]), v1 = up2(acc[2 * u + 1]);
        pp[(size_t)(4 * u + 0) * 768] = v0.x;
        pp[(size_t)(4 * u + 1) * 768] = v0.y;
        pp[(size_t)(4 * u + 2) * 768] = v1.x;
        pp[(size_t)(4 * u + 3) * 768] = v1.y;
    }
}

// ---------------------------------------------------------------- kernel 3: reduce + bias + sigmoid
// 384 blocks x 256 threads, 1 scalar/thread, 12 independent LDGs (MLP 12)
__global__ void __launch_bounds__(256) k_reduce(const float* __restrict__ bf,
                                                float* __restrict__ y) {
    const int i = blockIdx.x * 256 + threadIdx.x;  // 0..98303
    int o = i % 768;
    float v[12];
#pragma unroll
    for (int k = 0; k < 12; k++) v[k] = __ldg(g_part + (size_t)k * 98304 + i);
    float s01 = v[0] + v[1], s23 = v[2] + v[3], s45 = v[4] + v[5];
    float s67 = v[6] + v[7], s89 = v[8] + v[9], sab = v[10] + v[11];
    float s = ((s01 + s23) + (s45 + s67)) + ((s89 + sab) + __ldg(bf + o));
    y[i] = sig_fast(s);
}

// ---------------------------------------------------------------- launch
extern "C" void kernel_launch(void* const* d_in, const int* in_sizes, int n_in,
                              void* d_out, int out_size) {
    const float* x    = (const float*)d_in[0];  // (128, 768)
    const float* W    = (const float*)d_in[1];  // (3, 768, 768)
    const float* b    = (const float*)d_in[2];  // (3, 768)
    const float* lam  = (const float*)d_in[3];  // (3,)
    const float* eta0 = (const float*)d_in[4];  // (768, 768)
    const float* eta1 = (const float*)d_in[5];  // scalar
    const float* eta2 = (const float*)d_in[6];  // (768, 768)
    const float* wf   = (const float*)d_in[7];  // (768, 2304)
    const float* bf   = (const float*)d_in[8];  // (768,)
    const float* P0   = (const float*)d_in[9];  // (3, 768, 768)
    float* y = (float*)d_out;                   // (128, 768)

    k_scan<<<144, 256>>>(x, W, b, lam, eta0, eta1, eta2, P0, wf);
    k_gemm<<<dim3(3, 4, 12), 256>>>();
    k_reduce<<<384, 256>>>(bf, y);
}